// round 5
// baseline (speedup 1.0000x reference)
#include <cuda_runtime.h>
#include <cstdint>

#define L_LVL 4
#define B_SZ  128

static const size_t SLOT_Y  = 4ull * 128 * 1536;   // floats per gate-partial slot
static const size_t SLOT_UV = 4ull * 128 * 512;    // floats per uv-partial slot

// ---------------- scratch (static device arrays; no allocation) ----------------
__device__ float g_Y  [6ull * 4 * 128 * 1536];  // gate GEMM partials, 6 K-splits (18.9MB)
__device__ float g_UV [6ull * 4 * 128 * 512];   // u/v partials: slots 0-1 = xc, 2-5 = h splits
__device__ float g_UVf[4 * 128 * 512];          // final u|v with bias

__device__ __forceinline__ float sigm(float x) { return 1.f / (1.f + __expf(-x)); }
__device__ __forceinline__ uint32_t f2tf32(float x) {
    uint32_t r; asm("cvt.rna.tf32.f32 %0, %1;" : "=r"(r) : "f"(x)); return r;
}

// ---------------- tf32 tensor-core GEMM core, 2-stage pipeline, 1 sync/iter ----
// Y[m, n-tile] = A[m, 0:NIT*16] . W[n, wkoff : wkoff+NIT*16]   (W row stride 1536)
// BM=128, BN=128, BK=16. 256 threads = 8 warps (2m x 4n), warp tile 64x32.
#define BK   16
#define SROW 136

__device__ __forceinline__ void gemm_core(
    const float* __restrict__ Ab,                       // row stride 512, k-offset pre-applied
    const float* __restrict__ W0, const float* __restrict__ W1, const float* __restrict__ W2,
    int rowsPerMat, int NTOT, int wkoff, int NIT, int nt,
    float* __restrict__ Yslot)                          // + m*NTOT + n
{
    __shared__ uint32_t As[2][BK][SROW];
    __shared__ uint32_t Bs[2][BK][SROW];

    const int tid  = threadIdx.x;
    const int lane = tid & 31, warp = tid >> 5;
    const int m0w  = (warp & 1) * 64;
    const int n0w  = (warp >> 1) * 32;

    const int lm = tid & 127;
    const int kg = tid >> 7;
    const int kb = kg * 8;
    const float* arow = Ab + lm * 512 + kb;

    const int n_global = nt * 128 + lm;
    const int mat      = n_global / rowsPerMat;
    const int wrowi    = n_global % rowsPerMat;
    const float* Wb    = (mat == 0) ? W0 : ((mat == 1) ? W1 : W2);
    const float* wrow  = Wb + (size_t)wrowi * 1536 + wkoff + kb;

    float4 ra0, ra1, rb0, rb1;
    auto LD = [&](int t) {
        ra0 = __ldg((const float4*)(arow + t * BK));
        ra1 = __ldg((const float4*)(arow + t * BK + 4));
        rb0 = __ldg((const float4*)(wrow + t * BK));
        rb1 = __ldg((const float4*)(wrow + t * BK + 4));
    };
    auto ST = [&](int b) {
        As[b][kb + 0][lm] = f2tf32(ra0.x); As[b][kb + 1][lm] = f2tf32(ra0.y);
        As[b][kb + 2][lm] = f2tf32(ra0.z); As[b][kb + 3][lm] = f2tf32(ra0.w);
        As[b][kb + 4][lm] = f2tf32(ra1.x); As[b][kb + 5][lm] = f2tf32(ra1.y);
        As[b][kb + 6][lm] = f2tf32(ra1.z); As[b][kb + 7][lm] = f2tf32(ra1.w);
        Bs[b][kb + 0][lm] = f2tf32(rb0.x); Bs[b][kb + 1][lm] = f2tf32(rb0.y);
        Bs[b][kb + 2][lm] = f2tf32(rb0.z); Bs[b][kb + 3][lm] = f2tf32(rb0.w);
        Bs[b][kb + 4][lm] = f2tf32(rb1.x); Bs[b][kb + 5][lm] = f2tf32(rb1.y);
        Bs[b][kb + 6][lm] = f2tf32(rb1.z); Bs[b][kb + 7][lm] = f2tf32(rb1.w);
    };

    float acc[4][4][4];
#pragma unroll
    for (int i = 0; i < 4; i++)
#pragma unroll
        for (int j = 0; j < 4; j++)
#pragma unroll
            for (int f = 0; f < 4; f++) acc[i][j][f] = 0.f;

    const int fc  = lane & 3;
    const int frw = lane >> 2;

    LD(0); ST(0);
    LD(1);                    // NIT >= 2 always
    __syncthreads();

    for (int it = 0; it < NIT; it++) {
        const int nxt = it + 1;
        if (nxt < NIT) ST(nxt & 1);       // regs hold tile nxt; buffer nxt&1 is free (readers synced at it-1)
        if (it + 2 < NIT) LD(it + 2);     // prefetch 2 ahead

        const int buf = it & 1;
#pragma unroll
        for (int kk = 0; kk < BK; kk += 8) {
            uint32_t a[4][4], b[4][2];
#pragma unroll
            for (int mt = 0; mt < 4; mt++) {
                int m = m0w + mt * 16 + frw;
                a[mt][0] = As[buf][kk + fc][m];
                a[mt][1] = As[buf][kk + fc][m + 8];
                a[mt][2] = As[buf][kk + fc + 4][m];
                a[mt][3] = As[buf][kk + fc + 4][m + 8];
            }
#pragma unroll
            for (int ntt = 0; ntt < 4; ntt++) {
                int n = n0w + ntt * 8 + frw;
                b[ntt][0] = Bs[buf][kk + fc][n];
                b[ntt][1] = Bs[buf][kk + fc + 4][n];
            }
#pragma unroll
            for (int mt = 0; mt < 4; mt++)
#pragma unroll
                for (int ntt = 0; ntt < 4; ntt++) {
                    asm volatile(
                        "mma.sync.aligned.m16n8k8.row.col.f32.tf32.tf32.f32 "
                        "{%0,%1,%2,%3}, {%4,%5,%6,%7}, {%8,%9}, {%0,%1,%2,%3};"
                        : "+f"(acc[mt][ntt][0]), "+f"(acc[mt][ntt][1]),
                          "+f"(acc[mt][ntt][2]), "+f"(acc[mt][ntt][3])
                        : "r"(a[mt][0]), "r"(a[mt][1]), "r"(a[mt][2]), "r"(a[mt][3]),
                          "r"(b[ntt][0]), "r"(b[ntt][1]));
                }
        }
        __syncthreads();
    }

    const int colq = (lane & 3) * 2;
#pragma unroll
    for (int mt = 0; mt < 4; mt++) {
        int m = m0w + mt * 16 + frw;
        size_t base  = (size_t)m * NTOT + nt * 128 + n0w;
        size_t base2 = base + 8ull * NTOT;
#pragma unroll
        for (int ntt = 0; ntt < 4; ntt++) {
            *(float2*)&Yslot[base  + ntt * 8 + colq] = make_float2(acc[mt][ntt][0], acc[mt][ntt][1]);
            *(float2*)&Yslot[base2 + ntt * 8 + colq] = make_float2(acc[mt][ntt][2], acc[mt][ntt][3]);
        }
    }
}

// ---------------- launch 1: gate GEMM (6 K-splits) + u/v xc-part (independent) ----
// z 0..5 : gates. seg = z>>1 in {x,c,h}, kh = z&1 halves the 512 segment.
// z 6..7 : u/v from x (z=6) / c (z=7), full 512 K each. Only nt<4 used.
__global__ __launch_bounds__(256, 2) void gemm_stage1(
    const float* __restrict__ x, const float* __restrict__ c, const float* __restrict__ h,
    const float* __restrict__ phi_w, const float* __restrict__ alpha_w,
    const float* __restrict__ beta_w,
    const float* __restrict__ u_w, const float* __restrict__ v_w)
{
    const int nt = blockIdx.x, l = blockIdx.y, z = blockIdx.z;
    if (z < 6) {
        const int seg = z >> 1, kh = z & 1;
        const float* Ab = (seg == 0) ? x : (seg == 1) ? c : (h + (size_t)l * 65536);
        gemm_core(Ab + kh * 256,
                  phi_w   + (size_t)l * 512 * 1536,
                  alpha_w + (size_t)l * 512 * 1536,
                  beta_w  + (size_t)l * 512 * 1536,
                  512, 1536, seg * 512 + kh * 256, 16, nt,
                  g_Y + z * SLOT_Y + (size_t)l * 128 * 1536);
    } else {
        if (nt >= 4) return;
        const int s2 = z - 6;                       // 0: x, 1: c
        const float* Ab = s2 ? c : x;
        gemm_core(Ab,
                  u_w + (size_t)l * 256 * 1536,
                  v_w + (size_t)l * 256 * 1536,
                  v_w + (size_t)l * 256 * 1536,
                  256, 512, 512 + s2 * 512, 32, nt,
                  g_UV + s2 * SLOT_UV + (size_t)l * 128 * 512);
    }
}

// ---------------- launch 3: u/v h_new-part, 4 K-splits of 128 ----
__global__ __launch_bounds__(256, 2) void gemm_stage2(
    const float* __restrict__ hnew,
    const float* __restrict__ u_w, const float* __restrict__ v_w)
{
    const int nt = blockIdx.x, l = blockIdx.y, kh = blockIdx.z;
    gemm_core(hnew + (size_t)l * 65536 + kh * 128,
              u_w + (size_t)l * 256 * 1536,
              v_w + (size_t)l * 256 * 1536,
              v_w + (size_t)l * 256 * 1536,
              256, 512, kh * 128, 8, nt,
              g_UV + (2 + kh) * SLOT_UV + (size_t)l * 128 * 512);
}

// ---------------- gate epilogue: h_new = sig(a)*tanh(p) + sig(b)*h ----------------
__global__ void epi_gates(const float* __restrict__ phi_b, const float* __restrict__ alpha_b,
                          const float* __restrict__ beta_b, const float* __restrict__ h,
                          float* __restrict__ hnew)
{
    int i = blockIdx.x * blockDim.x + threadIdx.x;   // < 4*128*512
    int o  = i & 511;
    int lb = i >> 9;
    int l  = lb >> 7;
    size_t base = (size_t)lb * 1536;

    float p  = phi_b  [l*512 + o];
    float a  = alpha_b[l*512 + o];
    float bb = beta_b [l*512 + o];
#pragma unroll
    for (int z = 0; z < 6; z++) {
        size_t s = z * SLOT_Y + base;
        p  += g_Y[s + o];
        a  += g_Y[s + 512 + o];
        bb += g_Y[s + 1024 + o];
    }
    hnew[i] = sigm(a) * tanhf(p) + sigm(bb) * h[i];
}

// ---------------- u/v epilogue: sum 6 slots + bias ----------------
__global__ void epi_uv(const float* __restrict__ u_b, const float* __restrict__ v_b)
{
    int i = blockIdx.x * blockDim.x + threadIdx.x;   // < 4*128*512
    int n  = i & 511;
    int lb = i >> 9;
    int l  = lb >> 7;
    float s = 0.f;
#pragma unroll
    for (int sp = 0; sp < 6; sp++) s += g_UV[sp * SLOT_UV + i];
    s += (n < 256) ? u_b[l*256 + n] : v_b[l*256 + (n - 256)];
    g_UVf[i] = s;
}

// ---------------- fused M update ----------------
__device__ __forceinline__ float4 upd(float4 m, float4 ca, float4 cb,
                                      float g, float ee, float u, float4 v)
{
    float4 o;
    o.x = (1.f - g) * m.x + g * 0.5f * (ca.x + cb.x) + ee * u * v.x;
    o.y = (1.f - g) * m.y + g * 0.5f * (ca.y + cb.y) + ee * u * v.y;
    o.z = (1.f - g) * m.z + g * 0.5f * (ca.z + cb.z) + ee * u * v.z;
    o.w = (1.f - g) * m.w + g * 0.5f * (ca.w + cb.w) + ee * u * v.w;
    return o;
}

__global__ void mem_update(const float* __restrict__ M,
                           const float* __restrict__ gamma_logits,
                           const float* __restrict__ eta_logits,
                           float* __restrict__ outM)
{
    size_t idx = (size_t)blockIdx.x * blockDim.x + threadIdx.x;   // < 2097152
    size_t e = idx * 4;
    int b  = (int)(e >> 16);
    int rc = (int)(e & 65535);
    int r  = rc >> 8;
    int c  = rc & 255;
    const size_t LVL = 8388608ull;  // B*R*C

    float4 m0 = __ldg((const float4*)(M + e));
    float4 m1 = __ldg((const float4*)(M + LVL + e));
    float4 m2 = __ldg((const float4*)(M + 2*LVL + e));
    float4 m3 = __ldg((const float4*)(M + 3*LVL + e));

    float g0 = sigm(gamma_logits[0]), g1 = sigm(gamma_logits[1]);
    float g2 = sigm(gamma_logits[2]), g3 = sigm(gamma_logits[3]);
    float e0 = sigm(eta_logits[0]),   e1 = sigm(eta_logits[1]);
    float e2 = sigm(eta_logits[2]),   e3 = sigm(eta_logits[3]);

    float u0 = g_UVf[(0*128 + b)*512 + r];
    float u1 = g_UVf[(1*128 + b)*512 + r];
    float u2 = g_UVf[(2*128 + b)*512 + r];
    float u3 = g_UVf[(3*128 + b)*512 + r];
    float4 v0 = *(const float4*)&g_UVf[(0*128 + b)*512 + 256 + c];
    float4 v1 = *(const float4*)&g_UVf[(1*128 + b)*512 + 256 + c];
    float4 v2 = *(const float4*)&g_UVf[(2*128 + b)*512 + 256 + c];
    float4 v3 = *(const float4*)&g_UVf[(3*128 + b)*512 + 256 + c];

    // comm: l=0 -> (m0,m1); l=1 -> (m0,m2); l=2 -> (m1,m3); l=3 -> (m2,m3)
    *(float4*)(outM + e)           = upd(m0, m0, m1, g0, e0, u0, v0);
    *(float4*)(outM + LVL + e)     = upd(m1, m0, m2, g1, e1, u1, v1);
    *(float4*)(outM + 2*LVL + e)   = upd(m2, m1, m3, g2, e2, u2, v2);
    *(float4*)(outM + 3*LVL + e)   = upd(m3, m2, m3, g3, e3, u3, v3);
}

// ---------------- launch ----------------
extern "C" void kernel_launch(void* const* d_in, const int* in_sizes, int n_in,
                              void* d_out, int out_size)
{
    const float* x       = (const float*)d_in[0];
    const float* c       = (const float*)d_in[1];
    const float* h       = (const float*)d_in[2];
    const float* M       = (const float*)d_in[3];
    const float* phi_w   = (const float*)d_in[4];
    const float* phi_b   = (const float*)d_in[5];
    const float* alpha_w = (const float*)d_in[6];
    const float* alpha_b = (const float*)d_in[7];
    const float* beta_w  = (const float*)d_in[8];
    const float* beta_b  = (const float*)d_in[9];
    const float* u_w     = (const float*)d_in[10];
    const float* u_b     = (const float*)d_in[11];
    const float* v_w     = (const float*)d_in[12];
    const float* v_b     = (const float*)d_in[13];
    const float* gam     = (const float*)d_in[14];
    const float* eta     = (const float*)d_in[15];

    float* hnew = (float*)d_out;                 // (L,B,ST)
    float* outM = hnew + 4 * 128 * 512;          // (L,B,R,C)

    // 1) gates (6 splits) + u/v xc-part, one wave-filling launch
    gemm_stage1<<<dim3(12, 4, 8), 256>>>(x, c, h, phi_w, alpha_w, beta_w, u_w, v_w);
    // 2) h_new epilogue
    epi_gates<<<1024, 256>>>(phi_b, alpha_b, beta_b, h, hnew);
    // 3) u/v h_new-part (K=512, 4 splits)
    gemm_stage2<<<dim3(4, 4, 4), 256>>>(hnew, u_w, v_w);
    // 4) u/v sum + bias
    epi_uv<<<1024, 256>>>(u_b, v_b);
    // 5) fused memory update
    mem_update<<<8192, 256>>>(M, gam, eta, outM);
}

// round 6
// speedup vs baseline: 1.3632x; 1.3632x over previous
#include <cuda_runtime.h>
#include <cstdint>

#define L_LVL 4
#define B_SZ  128

static const size_t SLOT_Y  = 4ull * 128 * 1536;   // floats per gate-partial slot
static const size_t SLOT_UV = 4ull * 128 * 512;    // floats per uv-partial slot

// ---------------- scratch (static device arrays; no allocation) ----------------
__device__ float g_Y  [3ull * 4 * 128 * 1536];  // gate partials, 3 K-splits
__device__ float g_UV [6ull * 4 * 128 * 512];   // uv partials: 0-1 = x/c parts, 2-5 = h splits
__device__ float g_UVf[4 * 128 * 512];          // final u|v with bias

__device__ __forceinline__ float sigm(float x) { return 1.f / (1.f + __expf(-x)); }
__device__ __forceinline__ uint32_t f2tf32(float x) {
    uint32_t r; asm("cvt.rna.tf32.f32 %0, %1;" : "=r"(r) : "f"(x)); return r;
}
__device__ __forceinline__ void cpa16(uint32_t dst, const float* src) {
    asm volatile("cp.async.ca.shared.global [%0], [%1], 16;" :: "r"(dst), "l"(src));
}

// ---------------- tf32 GEMM core: cp.async 2-stage, BM=128 BN=128 BK=16 ------
// Y[m, nt*128 + n] = A[m, :16*NIT] . W[n, wkoff:+16*NIT]   (A stride 512, W stride 1536)
// 256 thr = 8 warps (2m x 4n), warp tile 64x32 of m16n8k8.
#define SKW 20   // 16 + 4 pad (words); keeps 16B alignment, conflict-free frags

__device__ __forceinline__ void gemm_core(
    const float* __restrict__ Ab,
    const float* __restrict__ W0, const float* __restrict__ W1, const float* __restrict__ W2,
    int rowsPerMat, int NTOT, int wkoff, int NIT, int nt,
    float* __restrict__ Yslot)
{
    __shared__ __align__(16) uint32_t As[2][128][SKW];
    __shared__ __align__(16) uint32_t Bs[2][128][SKW];

    const int tid  = threadIdx.x;
    const int lane = tid & 31, warp = tid >> 5;
    const int m0w  = (warp & 1) * 64;
    const int n0w  = (warp >> 1) * 32;

    // copy mapping: 2 threads per row; each thread 2x16B for A, 2x16B for B
    const int row = tid >> 1;
    const int kq  = (tid & 1) * 2;            // float4 index 0 or 2 within the 16-k tile
    const float* asrc = Ab + row * 512 + kq * 4;

    const int n_global = nt * 128 + row;
    const int mat      = n_global / rowsPerMat;
    const int wrowi    = n_global % rowsPerMat;
    const float* Wb    = (mat == 0) ? W0 : ((mat == 1) ? W1 : W2);
    const float* bsrc  = Wb + (size_t)wrowi * 1536 + wkoff + kq * 4;

    const uint32_t aD0 = (uint32_t)__cvta_generic_to_shared(&As[0][row][kq * 4]);
    const uint32_t bD0 = (uint32_t)__cvta_generic_to_shared(&Bs[0][row][kq * 4]);
    const uint32_t stg = (uint32_t)(128 * SKW * 4);   // bytes per stage

    auto ISSUE = [&](int t, int s) {
        const float* a = asrc + t * 16;
        const float* b = bsrc + t * 16;
        cpa16(aD0 + s * stg,      a);
        cpa16(aD0 + s * stg + 16, a + 4);
        cpa16(bD0 + s * stg,      b);
        cpa16(bD0 + s * stg + 16, b + 4);
        asm volatile("cp.async.commit_group;");
    };

    float acc[4][4][4];
#pragma unroll
    for (int i = 0; i < 4; i++)
#pragma unroll
        for (int j = 0; j < 4; j++)
#pragma unroll
            for (int f = 0; f < 4; f++) acc[i][j][f] = 0.f;

    const int fc  = lane & 3;
    const int frw = lane >> 2;

    ISSUE(0, 0);
    ISSUE(1, 1);
    asm volatile("cp.async.wait_group 1;");
    __syncthreads();

    for (int it = 0; it < NIT; it++) {
        const int buf = it & 1;
#pragma unroll
        for (int kk = 0; kk < 16; kk += 8) {
            uint32_t a[4][4], b[4][2];
#pragma unroll
            for (int mt = 0; mt < 4; mt++) {
                int m = m0w + mt * 16 + frw;
                a[mt][0] = f2tf32(__uint_as_float(As[buf][m    ][kk + fc]));
                a[mt][1] = f2tf32(__uint_as_float(As[buf][m + 8][kk + fc]));
                a[mt][2] = f2tf32(__uint_as_float(As[buf][m    ][kk + fc + 4]));
                a[mt][3] = f2tf32(__uint_as_float(As[buf][m + 8][kk + fc + 4]));
            }
#pragma unroll
            for (int ntt = 0; ntt < 4; ntt++) {
                int n = n0w + ntt * 8 + frw;
                b[ntt][0] = f2tf32(__uint_as_float(Bs[buf][n][kk + fc]));
                b[ntt][1] = f2tf32(__uint_as_float(Bs[buf][n][kk + fc + 4]));
            }
#pragma unroll
            for (int mt = 0; mt < 4; mt++)
#pragma unroll
                for (int ntt = 0; ntt < 4; ntt++) {
                    asm volatile(
                        "mma.sync.aligned.m16n8k8.row.col.f32.tf32.tf32.f32 "
                        "{%0,%1,%2,%3}, {%4,%5,%6,%7}, {%8,%9}, {%0,%1,%2,%3};"
                        : "+f"(acc[mt][ntt][0]), "+f"(acc[mt][ntt][1]),
                          "+f"(acc[mt][ntt][2]), "+f"(acc[mt][ntt][3])
                        : "r"(a[mt][0]), "r"(a[mt][1]), "r"(a[mt][2]), "r"(a[mt][3]),
                          "r"(b[ntt][0]), "r"(b[ntt][1]));
                }
        }
        __syncthreads();                       // all readers of buf done

        if (it + 2 < NIT) {
            ISSUE(it + 2, buf);                // overwrite freed buffer
            asm volatile("cp.async.wait_group 1;");   // tile it+1 resident
            __syncthreads();
        } else if (it + 1 < NIT) {
            asm volatile("cp.async.wait_group 0;");
            __syncthreads();
        }
    }

    const int colq = (lane & 3) * 2;
#pragma unroll
    for (int mt = 0; mt < 4; mt++) {
        int m = m0w + mt * 16 + frw;
        size_t base  = (size_t)m * NTOT + nt * 128 + n0w;
        size_t base2 = base + 8ull * NTOT;
#pragma unroll
        for (int ntt = 0; ntt < 4; ntt++) {
            *(float2*)&Yslot[base  + ntt * 8 + colq] = make_float2(acc[mt][ntt][0], acc[mt][ntt][1]);
            *(float2*)&Yslot[base2 + ntt * 8 + colq] = make_float2(acc[mt][ntt][2], acc[mt][ntt][3]);
        }
    }
}

// ---------------- launch 1: gates (3 K-splits) + uv xc-part ----------------
// z 0..2: gates, A = x/c/h_l, W cols z*512. z 3,4: uv from x/c (nt<4 only).
__global__ __launch_bounds__(256, 2) void gemm_stage1(
    const float* __restrict__ x, const float* __restrict__ c, const float* __restrict__ h,
    const float* __restrict__ phi_w, const float* __restrict__ alpha_w,
    const float* __restrict__ beta_w,
    const float* __restrict__ u_w, const float* __restrict__ v_w)
{
    const int nt = blockIdx.x, l = blockIdx.y, z = blockIdx.z;
    if (z < 3) {
        const float* Ab = (z == 0) ? x : (z == 1) ? c : (h + (size_t)l * 65536);
        gemm_core(Ab,
                  phi_w   + (size_t)l * 512 * 1536,
                  alpha_w + (size_t)l * 512 * 1536,
                  beta_w  + (size_t)l * 512 * 1536,
                  512, 1536, z * 512, 32, nt,
                  g_Y + z * SLOT_Y + (size_t)l * 128 * 1536);
    } else {
        if (nt >= 4) return;
        const int s2 = z - 3;                 // 0: x, 1: c
        gemm_core(s2 ? c : x,
                  u_w + (size_t)l * 256 * 1536,
                  v_w + (size_t)l * 256 * 1536,
                  v_w + (size_t)l * 256 * 1536,
                  256, 512, 512 + s2 * 512, 32, nt,
                  g_UV + s2 * SLOT_UV + (size_t)l * 128 * 512);
    }
}

// ---------------- launch 3: uv h_new-part, 4 K-splits of 128 ----------------
__global__ __launch_bounds__(256, 2) void gemm_stage2(
    const float* __restrict__ hnew,
    const float* __restrict__ u_w, const float* __restrict__ v_w)
{
    const int nt = blockIdx.x, l = blockIdx.y, kh = blockIdx.z;
    gemm_core(hnew + (size_t)l * 65536 + kh * 128,
              u_w + (size_t)l * 256 * 1536,
              v_w + (size_t)l * 256 * 1536,
              v_w + (size_t)l * 256 * 1536,
              256, 512, kh * 128, 8, nt,
              g_UV + (2 + kh) * SLOT_UV + (size_t)l * 128 * 512);
}

// ---------------- gate epilogue: h_new = sig(a)*tanh(p) + sig(b)*h ----------
__global__ void epi_gates(const float* __restrict__ phi_b, const float* __restrict__ alpha_b,
                          const float* __restrict__ beta_b, const float* __restrict__ h,
                          float* __restrict__ hnew)
{
    int i = blockIdx.x * blockDim.x + threadIdx.x;   // < 4*128*512
    int o  = i & 511;
    int lb = i >> 9;
    int l  = lb >> 7;
    size_t base = (size_t)lb * 1536;

    float p  = phi_b  [l*512 + o];
    float a  = alpha_b[l*512 + o];
    float bb = beta_b [l*512 + o];
#pragma unroll
    for (int z = 0; z < 3; z++) {
        size_t s = z * SLOT_Y + base;
        p  += g_Y[s + o];
        a  += g_Y[s + 512 + o];
        bb += g_Y[s + 1024 + o];
    }
    hnew[i] = sigm(a) * tanhf(p) + sigm(bb) * h[i];
}

// ---------------- u/v epilogue: sum 6 slots + bias ----------------
__global__ void epi_uv(const float* __restrict__ u_b, const float* __restrict__ v_b)
{
    int i = blockIdx.x * blockDim.x + threadIdx.x;   // < 4*128*512
    int n  = i & 511;
    int lb = i >> 9;
    int l  = lb >> 7;
    float s = 0.f;
#pragma unroll
    for (int sp = 0; sp < 6; sp++) s += g_UV[sp * SLOT_UV + i];
    s += (n < 256) ? u_b[l*256 + n] : v_b[l*256 + (n - 256)];
    g_UVf[i] = s;
}

// ---------------- fused M update ----------------
__device__ __forceinline__ float4 upd(float4 m, float4 ca, float4 cb,
                                      float g, float ee, float u, float4 v)
{
    float4 o;
    o.x = (1.f - g) * m.x + g * 0.5f * (ca.x + cb.x) + ee * u * v.x;
    o.y = (1.f - g) * m.y + g * 0.5f * (ca.y + cb.y) + ee * u * v.y;
    o.z = (1.f - g) * m.z + g * 0.5f * (ca.z + cb.z) + ee * u * v.z;
    o.w = (1.f - g) * m.w + g * 0.5f * (ca.w + cb.w) + ee * u * v.w;
    return o;
}

__global__ void mem_update(const float* __restrict__ M,
                           const float* __restrict__ gamma_logits,
                           const float* __restrict__ eta_logits,
                           float* __restrict__ outM)
{
    size_t idx = (size_t)blockIdx.x * blockDim.x + threadIdx.x;   // < 2097152
    size_t e = idx * 4;
    int b  = (int)(e >> 16);
    int rc = (int)(e & 65535);
    int r  = rc >> 8;
    int c  = rc & 255;
    const size_t LVL = 8388608ull;  // B*R*C

    float4 m0 = __ldg((const float4*)(M + e));
    float4 m1 = __ldg((const float4*)(M + LVL + e));
    float4 m2 = __ldg((const float4*)(M + 2*LVL + e));
    float4 m3 = __ldg((const float4*)(M + 3*LVL + e));

    float g0 = sigm(gamma_logits[0]), g1 = sigm(gamma_logits[1]);
    float g2 = sigm(gamma_logits[2]), g3 = sigm(gamma_logits[3]);
    float e0 = sigm(eta_logits[0]),   e1 = sigm(eta_logits[1]);
    float e2 = sigm(eta_logits[2]),   e3 = sigm(eta_logits[3]);

    float u0 = g_UVf[(0*128 + b)*512 + r];
    float u1 = g_UVf[(1*128 + b)*512 + r];
    float u2 = g_UVf[(2*128 + b)*512 + r];
    float u3 = g_UVf[(3*128 + b)*512 + r];
    float4 v0 = *(const float4*)&g_UVf[(0*128 + b)*512 + 256 + c];
    float4 v1 = *(const float4*)&g_UVf[(1*128 + b)*512 + 256 + c];
    float4 v2 = *(const float4*)&g_UVf[(2*128 + b)*512 + 256 + c];
    float4 v3 = *(const float4*)&g_UVf[(3*128 + b)*512 + 256 + c];

    // comm: l=0 -> (m0,m1); l=1 -> (m0,m2); l=2 -> (m1,m3); l=3 -> (m2,m3)
    *(float4*)(outM + e)           = upd(m0, m0, m1, g0, e0, u0, v0);
    *(float4*)(outM + LVL + e)     = upd(m1, m0, m2, g1, e1, u1, v1);
    *(float4*)(outM + 2*LVL + e)   = upd(m2, m1, m3, g2, e2, u2, v2);
    *(float4*)(outM + 3*LVL + e)   = upd(m3, m2, m3, g3, e3, u3, v3);
}

// ---------------- launch ----------------
extern "C" void kernel_launch(void* const* d_in, const int* in_sizes, int n_in,
                              void* d_out, int out_size)
{
    const float* x       = (const float*)d_in[0];
    const float* c       = (const float*)d_in[1];
    const float* h       = (const float*)d_in[2];
    const float* M       = (const float*)d_in[3];
    const float* phi_w   = (const float*)d_in[4];
    const float* phi_b   = (const float*)d_in[5];
    const float* alpha_w = (const float*)d_in[6];
    const float* alpha_b = (const float*)d_in[7];
    const float* beta_w  = (const float*)d_in[8];
    const float* beta_b  = (const float*)d_in[9];
    const float* u_w     = (const float*)d_in[10];
    const float* u_b     = (const float*)d_in[11];
    const float* v_w     = (const float*)d_in[12];
    const float* v_b     = (const float*)d_in[13];
    const float* gam     = (const float*)d_in[14];
    const float* eta     = (const float*)d_in[15];

    float* hnew = (float*)d_out;                 // (L,B,ST)
    float* outM = hnew + 4 * 128 * 512;          // (L,B,R,C)

    // 1) gates (3 K-splits) + u/v xc-part
    gemm_stage1<<<dim3(12, 4, 5), 256>>>(x, c, h, phi_w, alpha_w, beta_w, u_w, v_w);
    // 2) h_new epilogue
    epi_gates<<<1024, 256>>>(phi_b, alpha_b, beta_b, h, hnew);
    // 3) u/v h_new-part (K=512, 4 splits)
    gemm_stage2<<<dim3(4, 4, 4), 256>>>(hnew, u_w, v_w);
    // 4) u/v sum + bias
    epi_uv<<<1024, 256>>>(u_b, v_b);
    // 5) fused memory update
    mem_update<<<8192, 256>>>(M, gam, eta, outM);
}